// round 11
// baseline (speedup 1.0000x reference)
#include <cuda_runtime.h>
#include <cstdint>

#define T_STEPS 100
#define BATCH   256
#define IN_DIM  1024
#define HID     2048
#define OUT_DIM 10
#define BH      (BATCH * HID)
#define TBROWS  (T_STEPS * BATCH)
#define XL_MAX  512

// ---------------- scratch (device globals; no runtime allocation) ----------------
__device__ __align__(128) int8_t   g_X[(size_t)TBROWS * IN_DIM];
__device__ __align__(128) uint16_t g_xlist[(size_t)TBROWS * XL_MAX];   // ascending per row
__device__ __align__(128) int      g_xbnd[TBROWS * 5];                 // chunk starts (256-wide) + len
__device__ __align__(128) float    g_I0[(size_t)TBROWS * HID];
__device__ __align__(128) float    g_I1[BH];
__device__ __align__(128) float    g_v0[BH];
__device__ __align__(128) float    g_v1[BH];
__device__ __align__(128) float    g_vout[BATCH * OUT_DIM];
__device__ __align__(128) float    g_cnt[BATCH * OUT_DIM];
__device__ __align__(128) uint16_t g_s0list[BATCH * HID];              // ascending per b
__device__ __align__(128) int      g_s0bnd[BATCH * 5];                 // chunk starts (512-wide) + len

// ---------------- prep ----------------
__global__ void prep_x_k(const float* __restrict__ in0) {
    __shared__ float tile[32][33];
    const int b  = blockIdx.z;
    const int i0 = blockIdx.x * 32;
    const int t0 = blockIdx.y * 32;
    const int tx = threadIdx.x, ty = threadIdx.y;
    if (t0 + tx < T_STEPS)
        tile[ty][tx] = in0[((size_t)b * IN_DIM + (i0 + ty)) * T_STEPS + t0 + tx];
    __syncthreads();
    const int t = t0 + ty;
    if (t < T_STEPS)
        g_X[((size_t)t * BATCH + b) * IN_DIM + i0 + tx] = (tile[tx][ty] > 0.5f) ? 1 : 0;
}

// ascending spike-index lists + chunk boundaries (chunks of 256 over IN_DIM)
__global__ void build_xlist_k() {
    const int row  = blockIdx.x * (blockDim.x >> 5) + (threadIdx.x >> 5);
    const int lane = threadIdx.x & 31;
    if (row >= TBROWS) return;
    const int8_t* x = g_X + (size_t)row * IN_DIM;
    uint16_t* lst = g_xlist + (size_t)row * XL_MAX;
    int base = 0;
    if (lane == 0) g_xbnd[row * 5 + 0] = 0;
    for (int c = 0; c < IN_DIM / 32; c++) {
        if ((c & 7) == 0 && c > 0 && lane == 0)
            g_xbnd[row * 5 + (c >> 3)] = base < XL_MAX ? base : XL_MAX;
        const int k = c * 32 + lane;
        const bool sp = x[k] != 0;
        const unsigned m = __ballot_sync(0xffffffffu, sp);
        const int pos = __popc(m & ((1u << lane) - 1u));
        if (sp && base + pos < XL_MAX) lst[base + pos] = (uint16_t)k;
        base += __popc(m);
    }
    if (lane == 0) g_xbnd[row * 5 + 4] = base < XL_MAX ? base : XL_MAX;
}

__global__ void init_k() {
    const int i = blockIdx.x * blockDim.x + threadIdx.x;
    if (i < BH) { g_v0[i] = 0.f; g_v1[i] = 0.f; }
    if (i < BATCH * OUT_DIM) g_vout[i] = 0.f;
}

// ---------------- phase A: chunked-serial (S=4, chunk=256) layer-0 currents ----------------
// CTA = 32 n-cols x 256 rows; W_ih slice (128KB) L1-resident. 2 CTAs/SM via dummy dyn smem.
__global__ void __launch_bounds__(256) phaseA_k(const float* __restrict__ W) {
    const int q = threadIdx.x & 7, g = threadIdx.x >> 3;
    const int n = blockIdx.x * 32 + q * 4;
    const int rowbase = blockIdx.y * 256 + g * 8;
#pragma unroll 1
    for (int j = 0; j < 8; j++) {
        const int row = rowbase + j;
        const uint16_t* __restrict__ lst = g_xlist + (size_t)row * XL_MAX;
        const int* __restrict__ bnd = g_xbnd + row * 5;
        float r0, r1, r2, r3;
#pragma unroll
        for (int c = 0; c < 4; c++) {
            float s0 = 0.f, s1 = 0.f, s2 = 0.f, s3 = 0.f;
            const int e = bnd[c + 1];
            for (int i = bnd[c]; i < e; i++) {
                const float4 w = *(const float4*)(W + (size_t)lst[i] * HID + n);
                s0 = __fadd_rn(s0, w.x); s1 = __fadd_rn(s1, w.y);
                s2 = __fadd_rn(s2, w.z); s3 = __fadd_rn(s3, w.w);
            }
            if (c == 0) { r0 = s0; r1 = s1; r2 = s2; r3 = s3; }
            else {
                r0 = __fadd_rn(r0, s0); r1 = __fadd_rn(r1, s1);
                r2 = __fadd_rn(r2, s2); r3 = __fadd_rn(r3, s3);
            }
        }
        *(float4*)(g_I0 + (size_t)row * HID + n) = make_float4(r0, r1, r2, r3);
    }
}

// ---------------- per-step: LIF layer0 + ascending list + chunk bounds (CTA per b) ----------------
__global__ void __launch_bounds__(256) liflist0_k(const float* __restrict__ I) {
    __shared__ uint8_t fl[HID];
    __shared__ int wpre[9];
    const int b = blockIdx.x;
    const float* Ib = I + (size_t)b * HID;
    float* vb = g_v0 + (size_t)b * HID;
#pragma unroll
    for (int j = 0; j < 8; j++) {
        const int n = j * 256 + threadIdx.x;
        const float vv = __fadd_rn(__fmul_rn(vb[n], 0.9f), Ib[n]);
        const bool sp = vv >= 1.0f;
        vb[n] = sp ? 0.f : vv;
        fl[n] = sp ? 1 : 0;
    }
    __syncthreads();
    const int wid = threadIdx.x >> 5, lane = threadIdx.x & 31;
    int cnt = 0;
#pragma unroll
    for (int c = 0; c < 8; c++)
        cnt += __popc(__ballot_sync(0xffffffffu, fl[wid * 256 + c * 32 + lane] != 0));
    if (lane == 0) wpre[wid] = cnt;
    __syncthreads();
    if (threadIdx.x == 0) {
        int s = 0;
#pragma unroll
        for (int w = 0; w < 8; w++) { const int c = wpre[w]; wpre[w] = s; s += c; }
        wpre[8] = s;
#pragma unroll
        for (int c = 0; c < 4; c++) g_s0bnd[b * 5 + c] = wpre[2 * c];
        g_s0bnd[b * 5 + 4] = s;
    }
    __syncthreads();
    int base = wpre[wid];
#pragma unroll
    for (int c = 0; c < 8; c++) {
        const int n = wid * 256 + c * 32 + lane;
        const bool sp = fl[n] != 0;
        const unsigned m = __ballot_sync(0xffffffffu, sp);
        const int pos = __popc(m & ((1u << lane) - 1u));
        if (sp) g_s0list[b * HID + base + pos] = (uint16_t)n;
        base += __popc(m);
    }
}

// ---------------- per-step hidden: chunked-serial (S=4, chunk=512), L1-resident W slice ----------------
// CTA = 16 n-cols x 256 b; grid 128. W_hh slice 2048x16x4B = 128KB per CTA (read from L2 once).
__global__ void __launch_bounds__(256) hidden_k(const float* __restrict__ W) {
    const int quad = threadIdx.x & 3, bg = threadIdx.x >> 2;
    const int n = blockIdx.x * 16 + quad * 4;
#pragma unroll 1
    for (int j = 0; j < 4; j++) {
        const int b = bg * 4 + j;
        const uint16_t* __restrict__ lst = g_s0list + b * HID;
        const int* __restrict__ bnd = g_s0bnd + b * 5;
        float r0, r1, r2, r3;
#pragma unroll
        for (int c = 0; c < 4; c++) {
            float s0 = 0.f, s1 = 0.f, s2 = 0.f, s3 = 0.f;
            const int e = bnd[c + 1];
            for (int i = bnd[c]; i < e; i++) {
                const float4 w = *(const float4*)(W + (size_t)lst[i] * HID + n);
                s0 = __fadd_rn(s0, w.x); s1 = __fadd_rn(s1, w.y);
                s2 = __fadd_rn(s2, w.z); s3 = __fadd_rn(s3, w.w);
            }
            if (c == 0) { r0 = s0; r1 = s1; r2 = s2; r3 = s3; }
            else {
                r0 = __fadd_rn(r0, s0); r1 = __fadd_rn(r1, s1);
                r2 = __fadd_rn(r2, s2); r3 = __fadd_rn(r3, s3);
            }
        }
        *(float4*)(g_I1 + (size_t)b * HID + n) = make_float4(r0, r1, r2, r3);
    }
}

// ---------------- per-step: LIF layer1 + output gather (fp64 exact) + LIF out + rate ----------------
__global__ void __launch_bounds__(256) lif1out_k(const float* __restrict__ Who, int t,
                                                 float* __restrict__ d_out) {
    const int b = blockIdx.x;
    const int tid = threadIdx.x;
    double acc[OUT_DIM];
#pragma unroll
    for (int q = 0; q < OUT_DIM; q++) acc[q] = 0.0;
#pragma unroll
    for (int j = 0; j < 8; j++) {
        const int n = j * 256 + tid;
        const size_t o = (size_t)b * HID + n;
        const float vv = __fadd_rn(__fmul_rn(g_v1[o], 0.9f), g_I1[o]);
        const bool sp = vv >= 1.0f;
        g_v1[o] = sp ? 0.f : vv;
        if (sp) {
#pragma unroll
            for (int q = 0; q < OUT_DIM; q++) acc[q] += (double)__ldg(Who + n * OUT_DIM + q);
        }
    }
    __shared__ double sred[OUT_DIM][8];
#pragma unroll
    for (int off = 16; off > 0; off >>= 1)
#pragma unroll
        for (int q = 0; q < OUT_DIM; q++)
            acc[q] += __shfl_down_sync(0xffffffffu, acc[q], off);
    if ((tid & 31) == 0)
#pragma unroll
        for (int q = 0; q < OUT_DIM; q++) sred[q][tid >> 5] = acc[q];
    __syncthreads();
    if (tid < OUT_DIM) {
        const double curd = ((sred[tid][0] + sred[tid][1]) + (sred[tid][2] + sred[tid][3]))
                          + ((sred[tid][4] + sred[tid][5]) + (sred[tid][6] + sred[tid][7]));
        const int o = b * OUT_DIM + tid;
        const float vo = __fadd_rn(__fmul_rn(g_vout[o], 0.9f), (float)curd);
        const bool sp = vo >= 1.0f;
        g_vout[o] = sp ? 0.f : vo;
        const float c = (t == 0 ? 0.f : g_cnt[o]) + (sp ? 1.f : 0.f);
        if (t == T_STEPS - 1) d_out[o] = c / 100.0f;
        else g_cnt[o] = c;
    }
}

// ---------------- launch ----------------
extern "C" void kernel_launch(void* const* d_in, const int* in_sizes, int n_in,
                              void* d_out, int out_size) {
    (void)in_sizes; (void)n_in; (void)out_size;
    const float* in_bins = (const float*)d_in[0];
    const float* W_ih    = (const float*)d_in[1];
    const float* W_hh    = (const float*)d_in[2];
    const float* W_ho    = (const float*)d_in[3];
    float* out = (float*)d_out;

    // occupancy cap for phaseA (protect L1-resident W slice): 80KB dummy dyn smem -> 2 CTAs/SM
    const int PA_SMEM = 80 * 1024;
    cudaFuncSetAttribute(phaseA_k, cudaFuncAttributeMaxDynamicSharedMemorySize, PA_SMEM);

    void* pI0;
    cudaGetSymbolAddress(&pI0, g_I0);

    init_k<<<2048, 256>>>();
    prep_x_k<<<dim3(IN_DIM / 32, 4, BATCH), dim3(32, 32)>>>(in_bins);
    build_xlist_k<<<(TBROWS + 7) / 8, 256>>>();

    phaseA_k<<<dim3(HID / 32, TBROWS / 256), 256, PA_SMEM>>>(W_ih);

    for (int t = 0; t < T_STEPS; t++) {
        liflist0_k<<<BATCH, 256>>>((const float*)pI0 + (size_t)t * BH);
        hidden_k<<<HID / 16, 256>>>(W_hh);
        lif1out_k<<<BATCH, 256>>>(W_ho, t, out);
    }
}

// round 13
// speedup vs baseline: 1.8888x; 1.8888x over previous
#include <cuda_runtime.h>
#include <cstdint>

#define T_STEPS 100
#define BATCH   256
#define IN_DIM  1024
#define HID     2048
#define OUT_DIM 10
#define BH      (BATCH * HID)
#define TBROWS  (T_STEPS * BATCH)
#define XL_MAX  512

// ---------------- scratch (device globals; no runtime allocation) ----------------
__device__ __align__(128) int8_t   g_X[(size_t)TBROWS * IN_DIM];
__device__ __align__(128) uint16_t g_xlist[(size_t)TBROWS * XL_MAX];   // ascending per row
__device__ __align__(128) int      g_xbnd[TBROWS * 5];                 // 256-chunk starts + len
__device__ __align__(128) float    g_I0p[4ull * TBROWS * HID];         // layer-0 chunk partials [c][row][n]
__device__ __align__(128) float    g_hp[4ull * BATCH * HID];           // hidden chunk partials [c][b][n]
__device__ __align__(128) float    g_v0[BH];
__device__ __align__(128) float    g_v1[BH];
__device__ __align__(128) float    g_vout[BATCH * OUT_DIM];
__device__ __align__(128) float    g_cnt[BATCH * OUT_DIM];
__device__ __align__(128) uint16_t g_s0list[BATCH * HID];              // ascending per b
__device__ __align__(128) int      g_s0bnd[BATCH * 5];                 // 512-chunk starts + len

// ---------------- prep ----------------
__global__ void prep_x_k(const float* __restrict__ in0) {
    __shared__ float tile[32][33];
    const int b  = blockIdx.z;
    const int i0 = blockIdx.x * 32;
    const int t0 = blockIdx.y * 32;
    const int tx = threadIdx.x, ty = threadIdx.y;
    if (t0 + tx < T_STEPS)
        tile[ty][tx] = in0[((size_t)b * IN_DIM + (i0 + ty)) * T_STEPS + t0 + tx];
    __syncthreads();
    const int t = t0 + ty;
    if (t < T_STEPS)
        g_X[((size_t)t * BATCH + b) * IN_DIM + i0 + tx] = (tile[tx][ty] > 0.5f) ? 1 : 0;
}

__global__ void build_xlist_k() {
    const int row  = blockIdx.x * (blockDim.x >> 5) + (threadIdx.x >> 5);
    const int lane = threadIdx.x & 31;
    if (row >= TBROWS) return;
    const int8_t* x = g_X + (size_t)row * IN_DIM;
    uint16_t* lst = g_xlist + (size_t)row * XL_MAX;
    int base = 0;
    if (lane == 0) g_xbnd[row * 5 + 0] = 0;
    for (int c = 0; c < IN_DIM / 32; c++) {
        if ((c & 7) == 0 && c > 0 && lane == 0)
            g_xbnd[row * 5 + (c >> 3)] = base < XL_MAX ? base : XL_MAX;
        const int k = c * 32 + lane;
        const bool sp = x[k] != 0;
        const unsigned m = __ballot_sync(0xffffffffu, sp);
        const int pos = __popc(m & ((1u << lane) - 1u));
        if (sp && base + pos < XL_MAX) lst[base + pos] = (uint16_t)k;
        base += __popc(m);
    }
    if (lane == 0) g_xbnd[row * 5 + 4] = base < XL_MAX ? base : XL_MAX;
}

__global__ void init_k() {
    const int i = blockIdx.x * blockDim.x + threadIdx.x;
    if (i < BH) { g_v0[i] = 0.f; g_v1[i] = 0.f; }
    if (i < BATCH * OUT_DIM) g_vout[i] = 0.f;
}

// ---------------- phase A: per-chunk serial partials ----------------
// CTA = (32 n-cols, chunk c, 256 rows). W slice footprint = 256k x 128B = 32KB -> L1-resident,
// multiple distinct slices co-reside. Grid (64, 4, 100).
__global__ void __launch_bounds__(256) phaseA_k(const float* __restrict__ W) {
    const int q  = threadIdx.x & 7;        // n-quad within 32-col slice
    const int rg = threadIdx.x >> 3;       // 32 row-groups
    const int n = blockIdx.x * 32 + q * 4;
    const int c = blockIdx.y;
    const int row0 = blockIdx.z * 256 + rg * 8;
    float* __restrict__ out = g_I0p + (size_t)c * TBROWS * HID;
#pragma unroll 1
    for (int j = 0; j < 8; j++) {
        const int row = row0 + j;
        const uint16_t* __restrict__ lst = g_xlist + (size_t)row * XL_MAX;
        const int s = g_xbnd[row * 5 + c], e = g_xbnd[row * 5 + c + 1];
        float s0 = 0.f, s1 = 0.f, s2 = 0.f, s3 = 0.f;
        for (int i = s; i < e; i++) {
            const float4 w = *(const float4*)(W + (size_t)lst[i] * HID + n);
            s0 = __fadd_rn(s0, w.x); s1 = __fadd_rn(s1, w.y);
            s2 = __fadd_rn(s2, w.z); s3 = __fadd_rn(s3, w.w);
        }
        *(float4*)(out + (size_t)row * HID + n) = make_float4(s0, s1, s2, s3);
    }
}

// ---------------- per-step: combine layer-0 partials (LTR) + LIF + ascending list ----------------
__global__ void __launch_bounds__(256) liflist0_k(int t) {
    __shared__ uint8_t fl[HID];
    __shared__ int wpre[9];
    const int b = blockIdx.x;
    const size_t rowoff = ((size_t)t * BATCH + b) * HID;
    float* vb = g_v0 + (size_t)b * HID;
#pragma unroll
    for (int j = 0; j < 8; j++) {
        const int n = j * 256 + threadIdx.x;
        const float p0 = g_I0p[rowoff + n];
        const float p1 = g_I0p[(size_t)TBROWS * HID + rowoff + n];
        const float p2 = g_I0p[2ull * TBROWS * HID + rowoff + n];
        const float p3 = g_I0p[3ull * TBROWS * HID + rowoff + n];
        const float cur = __fadd_rn(__fadd_rn(__fadd_rn(p0, p1), p2), p3);
        const float vv = __fadd_rn(__fmul_rn(vb[n], 0.9f), cur);
        const bool sp = vv >= 1.0f;
        vb[n] = sp ? 0.f : vv;
        fl[n] = sp ? 1 : 0;
    }
    __syncthreads();
    const int wid = threadIdx.x >> 5, lane = threadIdx.x & 31;
    int cnt = 0;
#pragma unroll
    for (int c = 0; c < 8; c++)
        cnt += __popc(__ballot_sync(0xffffffffu, fl[wid * 256 + c * 32 + lane] != 0));
    if (lane == 0) wpre[wid] = cnt;
    __syncthreads();
    if (threadIdx.x == 0) {
        int s = 0;
#pragma unroll
        for (int w = 0; w < 8; w++) { const int c = wpre[w]; wpre[w] = s; s += c; }
        wpre[8] = s;
#pragma unroll
        for (int c = 0; c < 4; c++) g_s0bnd[b * 5 + c] = wpre[2 * c];
        g_s0bnd[b * 5 + 4] = s;
    }
    __syncthreads();
    int base = wpre[wid];
#pragma unroll
    for (int c = 0; c < 8; c++) {
        const int n = wid * 256 + c * 32 + lane;
        const bool sp = fl[n] != 0;
        const unsigned m = __ballot_sync(0xffffffffu, sp);
        const int pos = __popc(m & ((1u << lane) - 1u));
        if (sp) g_s0list[b * HID + base + pos] = (uint16_t)n;
        base += __popc(m);
    }
}

// ---------------- per-step hidden: per-chunk serial partials ----------------
// CTA = (32 n-cols, chunk c) over all 256 b. W slice footprint = 512k x 128B = 64KB -> L1-resident.
// Grid (64, 4) = 256 CTAs.
__global__ void __launch_bounds__(256) hidden_k(const float* __restrict__ W) {
    const int q  = threadIdx.x & 7;
    const int bg = threadIdx.x >> 3;       // 32 b-groups x 8 b
    const int n = blockIdx.x * 32 + q * 4;
    const int c = blockIdx.y;
    float* __restrict__ out = g_hp + (size_t)c * BH;
#pragma unroll 1
    for (int j = 0; j < 8; j++) {
        const int b = bg * 8 + j;
        const uint16_t* __restrict__ lst = g_s0list + b * HID;
        const int s = g_s0bnd[b * 5 + c], e = g_s0bnd[b * 5 + c + 1];
        float s0 = 0.f, s1 = 0.f, s2 = 0.f, s3 = 0.f;
        for (int i = s; i < e; i++) {
            const float4 w = *(const float4*)(W + (size_t)lst[i] * HID + n);
            s0 = __fadd_rn(s0, w.x); s1 = __fadd_rn(s1, w.y);
            s2 = __fadd_rn(s2, w.z); s3 = __fadd_rn(s3, w.w);
        }
        *(float4*)(out + (size_t)b * HID + n) = make_float4(s0, s1, s2, s3);
    }
}

// ---------------- per-step: combine hidden partials (LTR) + LIF1 + output (fp64) + LIF out ----------------
__global__ void __launch_bounds__(256) lif1out_k(const float* __restrict__ Who, int t,
                                                 float* __restrict__ d_out) {
    const int b = blockIdx.x;
    const int tid = threadIdx.x;
    double acc[OUT_DIM];
#pragma unroll
    for (int q = 0; q < OUT_DIM; q++) acc[q] = 0.0;
#pragma unroll
    for (int j = 0; j < 8; j++) {
        const int n = j * 256 + tid;
        const size_t o = (size_t)b * HID + n;
        const float p0 = g_hp[o];
        const float p1 = g_hp[(size_t)BH + o];
        const float p2 = g_hp[2ull * BH + o];
        const float p3 = g_hp[3ull * BH + o];
        const float cur = __fadd_rn(__fadd_rn(__fadd_rn(p0, p1), p2), p3);
        const float vv = __fadd_rn(__fmul_rn(g_v1[o], 0.9f), cur);
        const bool sp = vv >= 1.0f;
        g_v1[o] = sp ? 0.f : vv;
        if (sp) {
#pragma unroll
            for (int q = 0; q < OUT_DIM; q++) acc[q] += (double)__ldg(Who + n * OUT_DIM + q);
        }
    }
    __shared__ double sred[OUT_DIM][8];
#pragma unroll
    for (int off = 16; off > 0; off >>= 1)
#pragma unroll
        for (int q = 0; q < OUT_DIM; q++)
            acc[q] += __shfl_down_sync(0xffffffffu, acc[q], off);
    if ((tid & 31) == 0)
#pragma unroll
        for (int q = 0; q < OUT_DIM; q++) sred[q][tid >> 5] = acc[q];
    __syncthreads();
    if (tid < OUT_DIM) {
        const double curd = ((sred[tid][0] + sred[tid][1]) + (sred[tid][2] + sred[tid][3]))
                          + ((sred[tid][4] + sred[tid][5]) + (sred[tid][6] + sred[tid][7]));
        const int o = b * OUT_DIM + tid;
        const float vo = __fadd_rn(__fmul_rn(g_vout[o], 0.9f), (float)curd);
        const bool sp = vo >= 1.0f;
        g_vout[o] = sp ? 0.f : vo;
        const float c = (t == 0 ? 0.f : g_cnt[o]) + (sp ? 1.f : 0.f);
        if (t == T_STEPS - 1) d_out[o] = c / 100.0f;
        else g_cnt[o] = c;
    }
}

// ---------------- launch ----------------
extern "C" void kernel_launch(void* const* d_in, const int* in_sizes, int n_in,
                              void* d_out, int out_size) {
    (void)in_sizes; (void)n_in; (void)out_size;
    const float* in_bins = (const float*)d_in[0];
    const float* W_ih    = (const float*)d_in[1];
    const float* W_hh    = (const float*)d_in[2];
    const float* W_ho    = (const float*)d_in[3];
    float* out = (float*)d_out;

    init_k<<<2048, 256>>>();
    prep_x_k<<<dim3(IN_DIM / 32, 4, BATCH), dim3(32, 32)>>>(in_bins);
    build_xlist_k<<<(TBROWS + 7) / 8, 256>>>();

    // phase A: chunk partials for all 25600 rows (grid 64 n-slices x 4 chunks x 100 row-groups)
    phaseA_k<<<dim3(HID / 32, 4, TBROWS / 256), 256>>>(W_ih);

    for (int t = 0; t < T_STEPS; t++) {
        liflist0_k<<<BATCH, 256>>>(t);
        hidden_k<<<dim3(HID / 32, 4), 256>>>(W_hh);
        lif1out_k<<<BATCH, 256>>>(W_ho, t, out);
    }
}